// round 1
// baseline (speedup 1.0000x reference)
#include <cuda_runtime.h>
#include <cuda_bf16.h>

#define ACTIVE     32
#define HIDDEN     256          // per side
#define ACCDIM     512
#define NTHREADS   512
#define NWARPS     (NTHREADS / 32)

// dynamic smem layout:
//   sh_l1t : 512*32 floats  (l1_w transposed: [j][k])
//   sh_l2t : 32*32 floats   (l2_w transposed: [j][k])
//   sh_acc : NWARPS*512 floats (per-warp accumulator vector)
#define SMEM_L1T   (ACCDIM * 32)
#define SMEM_L2T   (32 * 32)
#define SMEM_ACC   (NWARPS * ACCDIM)
#define SMEM_FLOATS (SMEM_L1T + SMEM_L2T + SMEM_ACC)

__device__ __forceinline__ void add4(float4& a, const float4 b) {
    a.x += b.x; a.y += b.y; a.z += b.z; a.w += b.w;
}
__device__ __forceinline__ float4 sat4(float4 a) {
    return make_float4(__saturatef(a.x), __saturatef(a.y),
                       __saturatef(a.z), __saturatef(a.w));
}

__global__ __launch_bounds__(NTHREADS, 2)
void nnue_fused_kernel(
    const int*   __restrict__ white_idx,   // [B,32]
    const int*   __restrict__ black_idx,   // [B,32]
    const float* __restrict__ stm,         // [B,1]
    const float* __restrict__ ft_w,        // [40960,256]
    const float* __restrict__ ft_b,        // [256]
    const float* __restrict__ l1_w,        // [32,512]
    const float* __restrict__ l1_b,        // [32]
    const float* __restrict__ l2_w,        // [32,32]
    const float* __restrict__ l2_b,        // [32]
    const float* __restrict__ l3_w,        // [1,32]
    const float* __restrict__ l3_b,        // [1]
    float*       __restrict__ out,         // [B,1]
    int B)
{
    extern __shared__ float sm[];
    float* sh_l1t = sm;                      // [512][32]
    float* sh_l2t = sm + SMEM_L1T;           // [32][32]
    float* sh_acc = sm + SMEM_L1T + SMEM_L2T;

    const int tid = threadIdx.x;

    // Fill transposed weight tiles. Read pattern is strided (one-time, small).
    for (int idx = tid; idx < SMEM_L1T; idx += NTHREADS) {
        int j = idx >> 5, k = idx & 31;
        sh_l1t[idx] = l1_w[k * ACCDIM + j];
    }
    for (int idx = tid; idx < SMEM_L2T; idx += NTHREADS) {
        int j = idx >> 5, k = idx & 31;
        sh_l2t[idx] = l2_w[k * 32 + j];
    }
    __syncthreads();

    const int lane  = tid & 31;
    const int warp  = tid >> 5;
    const int gwarp = blockIdx.x * NWARPS + warp;
    const int wstride = gridDim.x * NWARPS;

    float* acc = sh_acc + warp * ACCDIM;
    float4* acc4 = (float4*)acc;
    const float4* acc4c = (const float4*)acc;

    // per-lane constants
    const float l1b = l1_b[lane];
    const float l2b = l2_b[lane];
    const float l3w = l3_w[lane];
    const float l3b = l3_b[0];
    const float4* ftb4 = (const float4*)ft_b;
    const float4 fb0 = ftb4[lane * 2];
    const float4 fb1 = ftb4[lane * 2 + 1];
    const float4* ftw4 = (const float4*)ft_w;   // 64 float4 per row

    for (int pos = gwarp; pos < B; pos += wstride) {
        // ---- feature transform: gather+sum 32 rows per side ----
        const int wi = white_idx[pos * ACTIVE + lane];
        const int bi = black_idx[pos * ACTIVE + lane];

        float4 w0 = make_float4(0.f, 0.f, 0.f, 0.f), w1 = w0;
        float4 b0 = w0, b1 = w0;

        #pragma unroll 8
        for (int j = 0; j < ACTIVE; j++) {
            const int iw = __shfl_sync(0xffffffffu, wi, j);
            const int ib = __shfl_sync(0xffffffffu, bi, j);
            const float4* rw = ftw4 + (long)iw * 64 + lane * 2;
            const float4* rb = ftw4 + (long)ib * 64 + lane * 2;
            float4 a = rw[0], c = rw[1];
            float4 d = rb[0], e = rb[1];
            add4(w0, a); add4(w1, c);
            add4(b0, d); add4(b1, e);
        }
        add4(w0, fb0); add4(w1, fb1);
        add4(b0, fb0); add4(b1, fb1);
        float4 cw0 = sat4(w0), cw1 = sat4(w1);
        float4 cb0 = sat4(b0), cb1 = sat4(b1);

        // ---- stm select: acc = stm ? [w,b] : [b,w] ----
        const float s = stm[pos];
        const bool wfirst = (s > 0.5f);
        acc4[lane * 2]          = wfirst ? cw0 : cb0;
        acc4[lane * 2 + 1]      = wfirst ? cw1 : cb1;
        acc4[64 + lane * 2]     = wfirst ? cb0 : cw0;
        acc4[64 + lane * 2 + 1] = wfirst ? cb1 : cw1;
        __syncwarp();

        // ---- L1: lane k computes output k = dot(acc[512], l1t[:,k]) ----
        float s1 = l1b;
        #pragma unroll 4
        for (int j4 = 0; j4 < ACCDIM / 4; j4++) {
            const float4 a = acc4c[j4];          // broadcast (no conflict)
            const int base = j4 * 128 + lane;    // conflict-free per lane
            s1 += a.x * sh_l1t[base]
                + a.y * sh_l1t[base + 32]
                + a.z * sh_l1t[base + 64]
                + a.w * sh_l1t[base + 96];
        }
        const float x1 = __saturatef(s1);
        __syncwarp();   // all lanes done reading acc before next pos overwrites

        // ---- L2: 32x32 via shfl broadcast ----
        float s2 = l2b;
        #pragma unroll
        for (int j = 0; j < 32; j++) {
            const float xj = __shfl_sync(0xffffffffu, x1, j);
            s2 += xj * sh_l2t[j * 32 + lane];
        }
        const float x2 = __saturatef(s2);

        // ---- L3: dot(32) via butterfly reduce ----
        float p = x2 * l3w;
        #pragma unroll
        for (int off = 16; off > 0; off >>= 1)
            p += __shfl_xor_sync(0xffffffffu, p, off);

        if (lane == 0)
            out[pos] = p + l3b;
    }
}

extern "C" void kernel_launch(void* const* d_in, const int* in_sizes, int n_in,
                              void* d_out, int out_size)
{
    const int*   white_idx = (const int*)  d_in[0];
    const int*   black_idx = (const int*)  d_in[1];
    const float* stm       = (const float*)d_in[2];
    const float* ft_w      = (const float*)d_in[3];
    const float* ft_b      = (const float*)d_in[4];
    const float* l1_w      = (const float*)d_in[5];
    const float* l1_b      = (const float*)d_in[6];
    const float* l2_w      = (const float*)d_in[7];
    const float* l2_b      = (const float*)d_in[8];
    const float* l3_w      = (const float*)d_in[9];
    const float* l3_b      = (const float*)d_in[10];
    float* out = (float*)d_out;

    const int B = in_sizes[0] / ACTIVE;

    const size_t smem_bytes = SMEM_FLOATS * sizeof(float);
    static bool attr_set = false;
    // Setting a func attribute is idempotent and capture-safe; doing it every
    // call keeps kernel_launch deterministic.
    cudaFuncSetAttribute(nnue_fused_kernel,
                         cudaFuncAttributeMaxDynamicSharedMemorySize,
                         (int)smem_bytes);
    (void)attr_set;

    // persistent grid: 2 CTAs/SM on 148-SM sm_100a
    const int grid = 296;
    nnue_fused_kernel<<<grid, NTHREADS, smem_bytes>>>(
        white_idx, black_idx, stm, ft_w, ft_b,
        l1_w, l1_b, l2_w, l2_b, l3_w, l3_b, out, B);
}

// round 2
// speedup vs baseline: 1.5653x; 1.5653x over previous
#include <cuda_runtime.h>
#include <cuda_bf16.h>

#define ACTIVE     32
#define HIDDEN     256
#define ACCDIM     512
#define NTHREADS   256
#define NWARPS     (NTHREADS / 32)
#define L1PAD      516            // row stride in floats (conflict-free LDS.128)

// dynamic smem layout (floats):
//   sh_l1w : 32 * 516          l1_w rows, padded     (66,048 B)
//   sh_l2t : 32 * 32           l2_w transposed        (4,096 B)
//   sh_acc : NWARPS * 2 * 512  two acc vectors/warp  (32,768 B)
#define SMEM_L1W   (32 * L1PAD)
#define SMEM_L2T   (32 * 32)
#define SMEM_ACC   (NWARPS * 2 * ACCDIM)
#define SMEM_FLOATS (SMEM_L1W + SMEM_L2T + SMEM_ACC)

__device__ __forceinline__ void add4(float4& a, const float4 b) {
    a.x += b.x; a.y += b.y; a.z += b.z; a.w += b.w;
}
__device__ __forceinline__ float4 sat4(float4 a) {
    return make_float4(__saturatef(a.x), __saturatef(a.y),
                       __saturatef(a.z), __saturatef(a.w));
}

__global__ __launch_bounds__(NTHREADS, 2)
void nnue_fused_kernel(
    const int*   __restrict__ white_idx,   // [B,32]
    const int*   __restrict__ black_idx,   // [B,32]
    const float* __restrict__ stm,         // [B,1]
    const float* __restrict__ ft_w,        // [40960,256]
    const float* __restrict__ ft_b,        // [256]
    const float* __restrict__ l1_w,        // [32,512]
    const float* __restrict__ l1_b,        // [32]
    const float* __restrict__ l2_w,        // [32,32]
    const float* __restrict__ l2_b,        // [32]
    const float* __restrict__ l3_w,        // [1,32]
    const float* __restrict__ l3_b,        // [1]
    float*       __restrict__ out,         // [B,1]
    int B)
{
    extern __shared__ float sm[];
    float* sh_l1w = sm;                         // [32][516]
    float* sh_l2t = sm + SMEM_L1W;              // [32][32] transposed: [j][k]
    float* sh_acc = sm + SMEM_L1W + SMEM_L2T;

    const int tid = threadIdx.x;

    // one-time fills
    for (int idx = tid; idx < 32 * ACCDIM; idx += NTHREADS) {
        int k = idx >> 9, j = idx & 511;
        sh_l1w[k * L1PAD + j] = l1_w[idx];
    }
    for (int idx = tid; idx < SMEM_L2T; idx += NTHREADS) {
        int j = idx >> 5, k = idx & 31;
        sh_l2t[idx] = l2_w[k * 32 + j];
    }
    __syncthreads();

    const int lane  = tid & 31;
    const int warp  = tid >> 5;
    const int gwarp = blockIdx.x * NWARPS + warp;
    const int wstride = gridDim.x * NWARPS;

    float4* acc0_4 = (float4*)(sh_acc + warp * 2 * ACCDIM);
    float4* acc1_4 = acc0_4 + (ACCDIM / 4);

    // per-lane constants: lane owns float4 slots {lane, lane+32} of each half
    const float l1b = l1_b[lane];
    const float l2b = l2_b[lane];
    const float l3w = l3_w[lane];
    const float l3b = l3_b[0];
    const float4* ftb4 = (const float4*)ft_b;
    const float4 fb0 = ftb4[lane];
    const float4 fb1 = ftb4[lane + 32];
    const float4* ftw4 = (const float4*)ft_w;   // 64 float4 per row
    const float* wrow = sh_l1w + lane * L1PAD;

    const int G = (B + 1) >> 1;   // position pairs

    for (int g = gwarp; g < G; g += wstride) {
        const int p0 = g * 2;
        const int p1 = p0 + 1;
        const bool have1 = (p1 < B);

        // ---- feature transform + select for both positions ----
        #pragma unroll
        for (int pp = 0; pp < 2; pp++) {
            const int pos = pp ? p1 : p0;
            if (pp && !have1) break;
            float4* accp = pp ? acc1_4 : acc0_4;

            const int wi = white_idx[pos * ACTIVE + lane];
            const int bi = black_idx[pos * ACTIVE + lane];

            float4 w0 = make_float4(0.f,0.f,0.f,0.f), w1 = w0;
            float4 b0 = w0, b1 = w0;

            #pragma unroll 8
            for (int j = 0; j < ACTIVE; j++) {
                const int iw = __shfl_sync(0xffffffffu, wi, j);
                const int ib = __shfl_sync(0xffffffffu, bi, j);
                const float4* rw = ftw4 + (long)iw * 64;
                const float4* rb = ftw4 + (long)ib * 64;
                float4 a = rw[lane],      c = rw[lane + 32];
                float4 d = rb[lane],      e = rb[lane + 32];
                add4(w0, a); add4(w1, c);
                add4(b0, d); add4(b1, e);
            }
            add4(w0, fb0); add4(w1, fb1);
            add4(b0, fb0); add4(b1, fb1);
            float4 cw0 = sat4(w0), cw1 = sat4(w1);
            float4 cb0 = sat4(b0), cb1 = sat4(b1);

            const float s = stm[pos];
            const bool wfirst = (s > 0.5f);
            // first half = slots [0,64), second half = [64,128); lane-consecutive STS.128
            accp[lane]           = wfirst ? cw0 : cb0;
            accp[lane + 32]      = wfirst ? cw1 : cb1;
            accp[64 + lane]      = wfirst ? cb0 : cw0;
            accp[64 + lane + 32] = wfirst ? cb1 : cw1;
        }
        __syncwarp();

        // ---- L1: lane k computes output k for both positions ----
        // weight float4 read once per j4, reused for both positions
        float p0x=0.f,p0y=0.f,p0z=0.f,p0w=0.f;
        float p1x=0.f,p1y=0.f,p1z=0.f,p1w=0.f;
        #pragma unroll 4
        for (int j4 = 0; j4 < ACCDIM / 4; j4++) {
            const float4 wv = *(const float4*)(wrow + 4 * j4);  // conflict-free
            const float4 a0 = acc0_4[j4];                        // broadcast
            const float4 a1 = acc1_4[j4];                        // broadcast
            p0x += a0.x * wv.x; p0y += a0.y * wv.y;
            p0z += a0.z * wv.z; p0w += a0.w * wv.w;
            p1x += a1.x * wv.x; p1y += a1.y * wv.y;
            p1z += a1.z * wv.z; p1w += a1.w * wv.w;
        }
        const float x1_0 = __saturatef(((p0x + p0y) + (p0z + p0w)) + l1b);
        const float x1_1 = __saturatef(((p1x + p1y) + (p1z + p1w)) + l1b);
        __syncwarp();   // acc reads done before next group's stores

        // ---- L2 + L3 for both positions ----
        #pragma unroll
        for (int pp = 0; pp < 2; pp++) {
            if (pp && !have1) break;
            const float x1 = pp ? x1_1 : x1_0;
            float s2 = l2b;
            #pragma unroll
            for (int j = 0; j < 32; j++) {
                const float xj = __shfl_sync(0xffffffffu, x1, j);
                s2 += xj * sh_l2t[j * 32 + lane];
            }
            const float x2 = __saturatef(s2);
            float p = x2 * l3w;
            #pragma unroll
            for (int off = 16; off > 0; off >>= 1)
                p += __shfl_xor_sync(0xffffffffu, p, off);
            if (lane == 0)
                out[pp ? p1 : p0] = p + l3b;
        }
    }
}

extern "C" void kernel_launch(void* const* d_in, const int* in_sizes, int n_in,
                              void* d_out, int out_size)
{
    const int*   white_idx = (const int*)  d_in[0];
    const int*   black_idx = (const int*)  d_in[1];
    const float* stm       = (const float*)d_in[2];
    const float* ft_w      = (const float*)d_in[3];
    const float* ft_b      = (const float*)d_in[4];
    const float* l1_w      = (const float*)d_in[5];
    const float* l1_b      = (const float*)d_in[6];
    const float* l2_w      = (const float*)d_in[7];
    const float* l2_b      = (const float*)d_in[8];
    const float* l3_w      = (const float*)d_in[9];
    const float* l3_b      = (const float*)d_in[10];
    float* out = (float*)d_out;

    const int B = in_sizes[0] / ACTIVE;

    const size_t smem_bytes = SMEM_FLOATS * sizeof(float);   // ~102.9 KB
    cudaFuncSetAttribute(nnue_fused_kernel,
                         cudaFuncAttributeMaxDynamicSharedMemorySize,
                         (int)smem_bytes);

    const int grid = 296;   // 2 CTAs/SM on 148 SMs
    nnue_fused_kernel<<<grid, NTHREADS, smem_bytes>>>(
        white_idx, black_idx, stm, ft_w, ft_b,
        l1_w, l1_b, l2_w, l2_b, l3_w, l3_b, out, B);
}

// round 5
// speedup vs baseline: 1.9594x; 1.2518x over previous
#include <cuda_runtime.h>
#include <cuda_fp16.h>

#define ACTIVE     32
#define HIDDEN     256
#define ACCDIM     512
#define NTHREADS   256
#define NWARPS     (NTHREADS / 32)
#define INPUTSZ    40960

// bit-cast helpers (the __half2_as_uint intrinsics don't exist in this toolkit)
__device__ __forceinline__ unsigned int h2_to_u32(__half2 h) {
    return *reinterpret_cast<unsigned int*>(&h);
}
__device__ __forceinline__ __half2 u32_to_h2(unsigned int u) {
    return *reinterpret_cast<__half2*>(&u);
}

// fp16 shadow of ft_w: 40960 rows x 256 halves = 512B/row = 32 uint4 per row.
__device__ uint4 g_ftw_h[INPUTSZ * 32];
// l1_w transposed+packed: [j4][k] -> 4 halves (j4*4..j4*4+3 of row k) as uint2.
__device__ uint2 g_l1w_h[128 * 32];

// dynamic smem (per CTA):
//   sh_w1h : 128*32 uint2  (32 KB)  packed L1 weights
//   sh_l2t : 32*32  float  ( 4 KB)  l2_w transposed [j][k]
//   sh_acc : NWARPS*2*512 float (32 KB) two acc vectors per warp
#define SMEM_W1H_U2  (128 * 32)
#define SMEM_L2T     (32 * 32)
#define SMEM_ACC     (NWARPS * 2 * ACCDIM)
#define SMEM_BYTES   (SMEM_W1H_U2 * 8 + (SMEM_L2T + SMEM_ACC) * 4)

__device__ __forceinline__ float satf(float x) { return __saturatef(x); }

// ---------- conversion kernels (run every call; deterministic) ----------
__global__ void convert_ftw_kernel(const float* __restrict__ ft_w, int n_u4)
{
    int i = blockIdx.x * blockDim.x + threadIdx.x;      // one uint4 = 8 halves
    if (i >= n_u4) return;
    const float4* src = (const float4*)ft_w;
    float4 a = src[2 * i];
    float4 b = src[2 * i + 1];
    uint4 o;
    o.x = h2_to_u32(__floats2half2_rn(a.x, a.y));
    o.y = h2_to_u32(__floats2half2_rn(a.z, a.w));
    o.z = h2_to_u32(__floats2half2_rn(b.x, b.y));
    o.w = h2_to_u32(__floats2half2_rn(b.z, b.w));
    g_ftw_h[i] = o;
}

__global__ void pack_l1w_kernel(const float* __restrict__ l1_w)
{
    int i = blockIdx.x * blockDim.x + threadIdx.x;      // i = j4*32 + k
    if (i >= 128 * 32) return;
    int j4 = i >> 5, k = i & 31;
    const float* r = l1_w + k * ACCDIM + j4 * 4;
    uint2 o;
    o.x = h2_to_u32(__floats2half2_rn(r[0], r[1]));
    o.y = h2_to_u32(__floats2half2_rn(r[2], r[3]));
    g_l1w_h[i] = o;
}

// ---------- main fused kernel ----------
__global__ __launch_bounds__(NTHREADS, 3)
void nnue_fused_kernel(
    const int*   __restrict__ white_idx,
    const int*   __restrict__ black_idx,
    const float* __restrict__ stm,
    const float* __restrict__ ft_b,
    const float* __restrict__ l2_w,
    const float* __restrict__ l1_b,
    const float* __restrict__ l2_b,
    const float* __restrict__ l3_w,
    const float* __restrict__ l3_b,
    float*       __restrict__ out,
    int B)
{
    extern __shared__ float sm[];
    uint2* sh_w1h = (uint2*)sm;                                   // [128][32]
    float* sh_l2t = sm + SMEM_W1H_U2 * 2;                         // [32][32]
    float* sh_acc = sh_l2t + SMEM_L2T;

    const int tid = threadIdx.x;

    for (int i = tid; i < SMEM_W1H_U2; i += NTHREADS)
        sh_w1h[i] = g_l1w_h[i];
    for (int i = tid; i < SMEM_L2T; i += NTHREADS) {
        int j = i >> 5, k = i & 31;
        sh_l2t[i] = l2_w[k * 32 + j];
    }
    __syncthreads();

    const int lane  = tid & 31;
    const int warp  = tid >> 5;
    const int gwarp = blockIdx.x * NWARPS + warp;
    const int wstride = gridDim.x * NWARPS;

    float4* acc0_4 = (float4*)(sh_acc + warp * 2 * ACCDIM);   // 128 float4
    float4* acc1_4 = acc0_4 + (ACCDIM / 4);                   // 128 float4

    const float l1b = l1_b[lane];
    const float l2b = l2_b[lane];
    const float l3w = l3_w[lane];
    const float l3b = l3_b[0];
    // lane owns columns [8*lane, 8*lane+8)
    const float4* ftb4 = (const float4*)ft_b;
    const float4 fbA = ftb4[2 * lane];
    const float4 fbB = ftb4[2 * lane + 1];

    const int G = B >> 1;   // B is even (pairs)

    for (int g = gwarp; g < G; g += wstride) {
        const int p0 = g * 2;
        const int p1 = p0 + 1;

        // ---- feature transform + select, both positions ----
        #pragma unroll
        for (int pp = 0; pp < 2; pp++) {
            const int pos = pp ? p1 : p0;
            float4* accp = pp ? acc1_4 : acc0_4;

            const int wi = white_idx[pos * ACTIVE + lane];
            const int bi = black_idx[pos * ACTIVE + lane];

            float w0=0.f,w1=0.f,w2=0.f,w3=0.f,w4=0.f,w5=0.f,w6=0.f,w7=0.f;
            float b0=0.f,b1=0.f,b2=0.f,b3=0.f,b4=0.f,b5=0.f,b6=0.f,b7=0.f;

            #pragma unroll 8
            for (int j = 0; j < ACTIVE; j++) {
                const int iw = __shfl_sync(0xffffffffu, wi, j);
                const int ib = __shfl_sync(0xffffffffu, bi, j);
                const uint4 rw = __ldg(&g_ftw_h[(long)iw * 32 + lane]);
                const uint4 rb = __ldg(&g_ftw_h[(long)ib * 32 + lane]);
                {
                    float2 f0 = __half22float2(u32_to_h2(rw.x));
                    float2 f1 = __half22float2(u32_to_h2(rw.y));
                    float2 f2 = __half22float2(u32_to_h2(rw.z));
                    float2 f3 = __half22float2(u32_to_h2(rw.w));
                    w0 += f0.x; w1 += f0.y; w2 += f1.x; w3 += f1.y;
                    w4 += f2.x; w5 += f2.y; w6 += f3.x; w7 += f3.y;
                }
                {
                    float2 f0 = __half22float2(u32_to_h2(rb.x));
                    float2 f1 = __half22float2(u32_to_h2(rb.y));
                    float2 f2 = __half22float2(u32_to_h2(rb.z));
                    float2 f3 = __half22float2(u32_to_h2(rb.w));
                    b0 += f0.x; b1 += f0.y; b2 += f1.x; b3 += f1.y;
                    b4 += f2.x; b5 += f2.y; b6 += f3.x; b7 += f3.y;
                }
            }
            float4 cw0 = make_float4(satf(w0+fbA.x), satf(w1+fbA.y),
                                     satf(w2+fbA.z), satf(w3+fbA.w));
            float4 cw1 = make_float4(satf(w4+fbB.x), satf(w5+fbB.y),
                                     satf(w6+fbB.z), satf(w7+fbB.w));
            float4 cb0 = make_float4(satf(b0+fbA.x), satf(b1+fbA.y),
                                     satf(b2+fbA.z), satf(b3+fbA.w));
            float4 cb1 = make_float4(satf(b4+fbB.x), satf(b5+fbB.y),
                                     satf(b6+fbB.z), satf(b7+fbB.w));

            const float s = stm[pos];
            const bool wfirst = (s > 0.5f);
            // first half (cols 0..255) = float4 slots [0,64); second half = [64,128)
            // lane's 8 cols = slots {2*lane, 2*lane+1} within each half
            accp[2*lane]             = wfirst ? cw0 : cb0;
            accp[2*lane + 1]         = wfirst ? cw1 : cb1;
            accp[64 + 2*lane]        = wfirst ? cb0 : cw0;
            accp[64 + 2*lane + 1]    = wfirst ? cb1 : cw1;
        }
        __syncwarp();

        // ---- L1: lane k computes output k for both positions ----
        float p00=0.f,p01=0.f,p02=0.f,p03=0.f;
        float p10=0.f,p11=0.f,p12=0.f,p13=0.f;
        #pragma unroll 4
        for (int j4 = 0; j4 < ACCDIM / 4; j4++) {
            const uint2 wp = sh_w1h[j4 * 32 + lane];       // 2-phase, conflict-free
            const float2 wlo = __half22float2(u32_to_h2(wp.x));
            const float2 whi = __half22float2(u32_to_h2(wp.y));
            const float4 a0 = acc0_4[j4];                  // broadcast
            const float4 a1 = acc1_4[j4];                  // broadcast
            p00 += a0.x * wlo.x; p01 += a0.y * wlo.y;
            p02 += a0.z * whi.x; p03 += a0.w * whi.y;
            p10 += a1.x * wlo.x; p11 += a1.y * wlo.y;
            p12 += a1.z * whi.x; p13 += a1.w * whi.y;
        }
        const float x1_0 = satf(((p00 + p01) + (p02 + p03)) + l1b);
        const float x1_1 = satf(((p10 + p11) + (p12 + p13)) + l1b);
        __syncwarp();   // acc reads done before next pair's stores

        // ---- L2 + L3 ----
        #pragma unroll
        for (int pp = 0; pp < 2; pp++) {
            const float x1 = pp ? x1_1 : x1_0;
            float s2 = l2b;
            #pragma unroll
            for (int j = 0; j < 32; j++) {
                const float xj = __shfl_sync(0xffffffffu, x1, j);
                s2 += xj * sh_l2t[j * 32 + lane];
            }
            const float x2 = satf(s2);
            float p = x2 * l3w;
            #pragma unroll
            for (int off = 16; off > 0; off >>= 1)
                p += __shfl_xor_sync(0xffffffffu, p, off);
            if (lane == 0)
                out[pp ? p1 : p0] = p + l3b;
        }
    }
}

extern "C" void kernel_launch(void* const* d_in, const int* in_sizes, int n_in,
                              void* d_out, int out_size)
{
    const int*   white_idx = (const int*)  d_in[0];
    const int*   black_idx = (const int*)  d_in[1];
    const float* stm       = (const float*)d_in[2];
    const float* ft_w      = (const float*)d_in[3];
    const float* ft_b      = (const float*)d_in[4];
    const float* l1_w      = (const float*)d_in[5];
    const float* l1_b      = (const float*)d_in[6];
    const float* l2_w      = (const float*)d_in[7];
    const float* l2_b      = (const float*)d_in[8];
    const float* l3_w      = (const float*)d_in[9];
    const float* l3_b      = (const float*)d_in[10];
    float* out = (float*)d_out;

    const int B = in_sizes[0] / ACTIVE;

    // 1) fp16 shadow table + packed L1 weights (every call; graph-capturable)
    const int n_u4 = INPUTSZ * 32;
    convert_ftw_kernel<<<(n_u4 + 255) / 256, 256>>>(ft_w, n_u4);
    pack_l1w_kernel<<<(128 * 32 + 255) / 256, 256>>>(l1_w);

    // 2) fused network
    cudaFuncSetAttribute(nnue_fused_kernel,
                         cudaFuncAttributeMaxDynamicSharedMemorySize,
                         (int)SMEM_BYTES);
    const int grid = 444;   // 3 CTAs/SM on 148 SMs
    nnue_fused_kernel<<<grid, NTHREADS, SMEM_BYTES>>>(
        white_idx, black_idx, stm, ft_b, l2_w,
        l1_b, l2_b, l3_w, l3_b, out, B);
}

// round 6
// speedup vs baseline: 1.9717x; 1.0062x over previous
#include <cuda_runtime.h>
#include <cuda_fp16.h>

#define ACTIVE     32
#define HIDDEN     256
#define ACCDIM     512
#define NTHREADS   256
#define NWARPS     (NTHREADS / 32)
#define INPUTSZ    40960

__device__ __forceinline__ unsigned int h2_to_u32(__half2 h) {
    return *reinterpret_cast<unsigned int*>(&h);
}
__device__ __forceinline__ __half2 u32_to_h2(unsigned int u) {
    return *reinterpret_cast<__half2*>(&u);
}
__device__ __forceinline__ float satf(float x) { return __saturatef(x); }

// packed f32x2 fused multiply-add (sm_100a; ptxas never emits this from C++)
__device__ __forceinline__ void fma_f32x2(unsigned long long& d,
                                          unsigned long long a,
                                          unsigned long long b) {
    asm("fma.rn.f32x2 %0, %1, %2, %0;" : "+l"(d) : "l"(a), "l"(b));
}
__device__ __forceinline__ float f32x2_hsum(unsigned long long v) {
    unsigned int lo, hi;
    asm("mov.b64 {%0,%1}, %2;" : "=r"(lo), "=r"(hi) : "l"(v));
    return __uint_as_float(lo) + __uint_as_float(hi);
}

// fp16 shadow of ft_w: 40960 rows x 256 halves = 512B/row = 32 uint4 per row.
__device__ uint4 g_ftw_h[INPUTSZ * 32];
// l1_w transposed fp32: [j4][k] -> float4 (cols 4j4..4j4+3 of output row k)
__device__ float4 g_l1w_f[128 * 32];

// dynamic smem (per CTA):
//   sh_w1f : 128*32 float4 (64 KB)  transposed fp32 L1 weights
//   sh_l2t : 32*32  float  ( 4 KB)  l2_w transposed [j][k]
//   sh_acc : NWARPS*2*512 float (32 KB) two acc vectors per warp
#define SMEM_W1F     (128 * 32)
#define SMEM_L2T     (32 * 32)
#define SMEM_ACC     (NWARPS * 2 * ACCDIM)
#define SMEM_BYTES   (SMEM_W1F * 16 + (SMEM_L2T + SMEM_ACC) * 4)

// ---------- conversion kernels (run every call; deterministic) ----------
__global__ void convert_ftw_kernel(const float* __restrict__ ft_w, int n_u4)
{
    int i = blockIdx.x * blockDim.x + threadIdx.x;      // one uint4 = 8 halves
    if (i >= n_u4) return;
    const float4* src = (const float4*)ft_w;
    float4 a = src[2 * i];
    float4 b = src[2 * i + 1];
    uint4 o;
    o.x = h2_to_u32(__floats2half2_rn(a.x, a.y));
    o.y = h2_to_u32(__floats2half2_rn(a.z, a.w));
    o.z = h2_to_u32(__floats2half2_rn(b.x, b.y));
    o.w = h2_to_u32(__floats2half2_rn(b.z, b.w));
    g_ftw_h[i] = o;
}

__global__ void pack_l1w_kernel(const float* __restrict__ l1_w)
{
    int i = blockIdx.x * blockDim.x + threadIdx.x;      // i = j4*32 + k
    if (i >= 128 * 32) return;
    int j4 = i >> 5, k = i & 31;
    const float* r = l1_w + k * ACCDIM + j4 * 4;
    g_l1w_f[i] = make_float4(r[0], r[1], r[2], r[3]);
}

// ---------- main fused kernel ----------
__global__ __launch_bounds__(NTHREADS, 2)
void nnue_fused_kernel(
    const int*   __restrict__ white_idx,
    const int*   __restrict__ black_idx,
    const float* __restrict__ stm,
    const float* __restrict__ ft_b,
    const float* __restrict__ l2_w,
    const float* __restrict__ l1_b,
    const float* __restrict__ l2_b,
    const float* __restrict__ l3_w,
    const float* __restrict__ l3_b,
    float*       __restrict__ out,
    int B)
{
    extern __shared__ float sm[];
    ulonglong2* sh_w1f = (ulonglong2*)sm;                 // [128][32] float4 as 2xf32x2
    float* sh_l2t = sm + SMEM_W1F * 4;                    // [32][32]
    float* sh_acc = sh_l2t + SMEM_L2T;

    const int tid = threadIdx.x;

    {
        const uint4* srcw = (const uint4*)g_l1w_f;
        uint4* dstw = (uint4*)sh_w1f;
        for (int i = tid; i < SMEM_W1F; i += NTHREADS)
            dstw[i] = srcw[i];
    }
    for (int i = tid; i < SMEM_L2T; i += NTHREADS) {
        int j = i >> 5, k = i & 31;
        sh_l2t[i] = l2_w[k * 32 + j];
    }
    __syncthreads();

    const int lane  = tid & 31;
    const int warp  = tid >> 5;
    const int gwarp = blockIdx.x * NWARPS + warp;
    const int wstride = gridDim.x * NWARPS;

    float4* acc0_4 = (float4*)(sh_acc + warp * 2 * ACCDIM);   // 128 float4
    float4* acc1_4 = acc0_4 + (ACCDIM / 4);
    const ulonglong2* acc0_u2 = (const ulonglong2*)acc0_4;
    const ulonglong2* acc1_u2 = (const ulonglong2*)acc1_4;

    const float l1b = l1_b[lane];
    const float l2b = l2_b[lane];
    const float l3w = l3_w[lane];
    const float l3b = l3_b[0];
    // lane owns columns [8*lane, 8*lane+8)
    const float4* ftb4 = (const float4*)ft_b;
    const float4 fbA = ftb4[2 * lane];
    const float4 fbB = ftb4[2 * lane + 1];

    const int G = B >> 1;

    for (int g = gwarp; g < G; g += wstride) {
        const int p0 = g * 2;
        const int p1 = p0 + 1;

        // ---- feature transform + select, both positions ----
        #pragma unroll
        for (int pp = 0; pp < 2; pp++) {
            const int pos = pp ? p1 : p0;
            float4* accp = pp ? acc1_4 : acc0_4;

            const int wi = white_idx[pos * ACTIVE + lane];
            const int bi = black_idx[pos * ACTIVE + lane];

            // fp32 running sums (8 per side)
            float w0=0.f,w1=0.f,w2=0.f,w3=0.f,w4=0.f,w5=0.f,w6=0.f,w7=0.f;
            float b0=0.f,b1=0.f,b2=0.f,b3=0.f,b4=0.f,b5=0.f,b6=0.f,b7=0.f;

            const __half2 hz = u32_to_h2(0u);

            // 8 chunks of 4 indices; accumulate each chunk in fp16 (HADD2),
            // combine chunk sums into fp32 (bounds the fp16 rounding growth)
            #pragma unroll
            for (int c = 0; c < 8; c++) {
                __half2 sw0=hz, sw1=hz, sw2=hz, sw3=hz;
                __half2 sb0=hz, sb1=hz, sb2=hz, sb3=hz;
                #pragma unroll
                for (int u = 0; u < 4; u++) {
                    const int j = c * 4 + u;
                    const int iw = __shfl_sync(0xffffffffu, wi, j);
                    const int ib = __shfl_sync(0xffffffffu, bi, j);
                    const uint4 rw = __ldg(&g_ftw_h[(long)iw * 32 + lane]);
                    const uint4 rb = __ldg(&g_ftw_h[(long)ib * 32 + lane]);
                    sw0 = __hadd2(sw0, u32_to_h2(rw.x));
                    sw1 = __hadd2(sw1, u32_to_h2(rw.y));
                    sw2 = __hadd2(sw2, u32_to_h2(rw.z));
                    sw3 = __hadd2(sw3, u32_to_h2(rw.w));
                    sb0 = __hadd2(sb0, u32_to_h2(rb.x));
                    sb1 = __hadd2(sb1, u32_to_h2(rb.y));
                    sb2 = __hadd2(sb2, u32_to_h2(rb.z));
                    sb3 = __hadd2(sb3, u32_to_h2(rb.w));
                }
                {
                    float2 f0 = __half22float2(sw0);
                    float2 f1 = __half22float2(sw1);
                    float2 f2 = __half22float2(sw2);
                    float2 f3 = __half22float2(sw3);
                    w0 += f0.x; w1 += f0.y; w2 += f1.x; w3 += f1.y;
                    w4 += f2.x; w5 += f2.y; w6 += f3.x; w7 += f3.y;
                }
                {
                    float2 f0 = __half22float2(sb0);
                    float2 f1 = __half22float2(sb1);
                    float2 f2 = __half22float2(sb2);
                    float2 f3 = __half22float2(sb3);
                    b0 += f0.x; b1 += f0.y; b2 += f1.x; b3 += f1.y;
                    b4 += f2.x; b5 += f2.y; b6 += f3.x; b7 += f3.y;
                }
            }

            float4 cw0 = make_float4(satf(w0+fbA.x), satf(w1+fbA.y),
                                     satf(w2+fbA.z), satf(w3+fbA.w));
            float4 cw1 = make_float4(satf(w4+fbB.x), satf(w5+fbB.y),
                                     satf(w6+fbB.z), satf(w7+fbB.w));
            float4 cb0 = make_float4(satf(b0+fbA.x), satf(b1+fbA.y),
                                     satf(b2+fbA.z), satf(b3+fbA.w));
            float4 cb1 = make_float4(satf(b4+fbB.x), satf(b5+fbB.y),
                                     satf(b6+fbB.z), satf(b7+fbB.w));

            const float s = stm[pos];
            const bool wfirst = (s > 0.5f);
            accp[2*lane]          = wfirst ? cw0 : cb0;
            accp[2*lane + 1]      = wfirst ? cw1 : cb1;
            accp[64 + 2*lane]     = wfirst ? cb0 : cw0;
            accp[64 + 2*lane + 1] = wfirst ? cb1 : cw1;
        }
        __syncwarp();

        // ---- L1: lane k computes output k for both positions (f32x2 FMA) ----
        unsigned long long q00 = 0ull, q01 = 0ull;   // pos0: (c0,c1),(c2,c3) partial pairs
        unsigned long long q10 = 0ull, q11 = 0ull;   // pos1
        const ulonglong2* wrow = sh_w1f + lane;
        #pragma unroll 4
        for (int j4 = 0; j4 < 128; j4++) {
            const ulonglong2 wv = wrow[j4 * 32];     // 16B/lane, 4-phase conflict-free
            const ulonglong2 a0 = acc0_u2[j4];       // broadcast
            const ulonglong2 a1 = acc1_u2[j4];       // broadcast
            fma_f32x2(q00, a0.x, wv.x);
            fma_f32x2(q01, a0.y, wv.y);
            fma_f32x2(q10, a1.x, wv.x);
            fma_f32x2(q11, a1.y, wv.y);
        }
        const float x1_0 = satf(f32x2_hsum(q00) + f32x2_hsum(q01) + l1b);
        const float x1_1 = satf(f32x2_hsum(q10) + f32x2_hsum(q11) + l1b);
        __syncwarp();   // acc reads done before next pair's stores

        // ---- L2 + L3 ----
        #pragma unroll
        for (int pp = 0; pp < 2; pp++) {
            const float x1 = pp ? x1_1 : x1_0;
            float s2 = l2b;
            #pragma unroll
            for (int j = 0; j < 32; j++) {
                const float xj = __shfl_sync(0xffffffffu, x1, j);
                s2 += xj * sh_l2t[j * 32 + lane];
            }
            const float x2 = satf(s2);
            float p = x2 * l3w;
            #pragma unroll
            for (int off = 16; off > 0; off >>= 1)
                p += __shfl_xor_sync(0xffffffffu, p, off);
            if (lane == 0)
                out[pp ? p1 : p0] = p + l3b;
        }
    }
}

extern "C" void kernel_launch(void* const* d_in, const int* in_sizes, int n_in,
                              void* d_out, int out_size)
{
    const int*   white_idx = (const int*)  d_in[0];
    const int*   black_idx = (const int*)  d_in[1];
    const float* stm       = (const float*)d_in[2];
    const float* ft_w      = (const float*)d_in[3];
    const float* ft_b      = (const float*)d_in[4];
    const float* l1_w      = (const float*)d_in[5];
    const float* l1_b      = (const float*)d_in[6];
    const float* l2_w      = (const float*)d_in[7];
    const float* l2_b      = (const float*)d_in[8];
    const float* l3_w      = (const float*)d_in[9];
    const float* l3_b      = (const float*)d_in[10];
    float* out = (float*)d_out;

    const int B = in_sizes[0] / ACTIVE;

    const int n_u4 = INPUTSZ * 32;
    convert_ftw_kernel<<<(n_u4 + 255) / 256, 256>>>(ft_w, n_u4);
    pack_l1w_kernel<<<(128 * 32 + 255) / 256, 256>>>(l1_w);

    cudaFuncSetAttribute(nnue_fused_kernel,
                         cudaFuncAttributeMaxDynamicSharedMemorySize,
                         (int)SMEM_BYTES);
    const int grid = 296;   // 2 CTAs/SM on 148 SMs
    nnue_fused_kernel<<<grid, NTHREADS, SMEM_BYTES>>>(
        white_idx, black_idx, stm, ft_b, l2_w,
        l1_b, l2_b, l3_w, l3_b, out, B);
}